// round 12
// baseline (speedup 1.0000x reference)
// R11 post-mortem: fma fill stuck at 45-47% because warps/SMSP × in-warp ILP
// was constant. New layout: 256 thr × 1 gate-row (64 weight regs) × 3 batches
// sharing weights -> ~125 regs, 2 CTAs/SM (4 warps/SMSP), 96 FFMA2 of
// independent work per warp between tails. Depth-1 gate exchange (xor 1/2/3).
#include <cuda_runtime.h>

#define Bn 4096
#define Tn 2048
#define Hn 64
#define NB 3                   // batches per CTA
#define NCTA ((Bn + NB - 1) / NB)   // 1366

// Device scratch (no allocs allowed).
__device__ float        g_partial[Bn];
__device__ int          g_perm[Bn];
__device__ unsigned int g_done = 0;   // self-resets via atomicInc wrap at NCTA

// ---------- packed f32x2 helpers (FFMA2 path, sm_103a) ----------
__device__ __forceinline__ unsigned long long pack2(float x, float y) {
    unsigned long long r;
    asm("mov.b64 %0, {%1, %2};" : "=l"(r) : "f"(x), "f"(y));
    return r;
}
__device__ __forceinline__ void unpack2(unsigned long long v, float& x, float& y) {
    asm("mov.b64 {%0, %1}, %2;" : "=f"(x), "=f"(y) : "l"(v));
}
__device__ __forceinline__ void ffma2(unsigned long long& d,
                                      unsigned long long a,
                                      unsigned long long b) {
    asm("fma.rn.f32x2 %0, %1, %2, %0;" : "+l"(d) : "l"(a), "l"(b));
}
__device__ __forceinline__ unsigned long long add2(unsigned long long a,
                                                   unsigned long long b) {
    unsigned long long r;
    asm("add.rn.f32x2 %0, %1, %2;" : "=l"(r) : "l"(a), "l"(b));
    return r;
}

// ---------- activations: hardware MUFU.TANH ----------
__device__ __forceinline__ float tanh_hw(float x) {
    float r;
    asm("tanh.approx.f32 %0, %1;" : "=f"(r) : "f"(x));
    return r;
}
__device__ __forceinline__ float sigm(float x) {
    return __fmaf_rn(tanh_hw(0.5f * x), 0.5f, 0.5f);
}

// ---------- seqlen counting sort (descending) -> g_perm ----------
// Output is invariant to intra-bucket order (batch elements independent).
__global__ void sort_kernel(const int* __restrict__ seql) {
    __shared__ int off[2049];
    int t = threadIdx.x;
    for (int i = t; i < 2049; i += 1024) off[i] = 0;
    __syncthreads();
    for (int i = t; i < Bn; i += 1024) atomicAdd(&off[seql[i]], 1);
    __syncthreads();
    if (t == 0) {
        int acc = 0;
        for (int v = 2048; v >= 1; v--) { int h = off[v]; off[v] = acc; acc += h; }
    }
    __syncthreads();
    for (int i = t; i < Bn; i += 1024) {
        int p = atomicAdd(&off[seql[i]], 1);
        g_perm[p] = i;
    }
}

// ============================================================================
// One CTA (256 threads) per TRIPLE of batch elements (sorted-adjacent lens).
// Thread t owns gate row (t&3)*64 + (t>>2); q=t&3: 0=i,1=f,2=g,3=o, so unit
// u's four gates sit on a lane quad -> 3 INDEPENDENT shfl_xor(1/2/3) bring
// sig(f), tanh(g), sig(o) to the qi==0 lane (depth-1 exchange).
// Weights register-resident, shared by all 3 recurrences. One barrier per
// step-triple; h ping-pongs per batch. Decoder rank-1 fold removes y->x from
// the critical path; warps 0/1/2 emit y for b0/b1/b2 one step late.
// ============================================================================
__global__ __launch_bounds__(256, 2)
void lstm_kernel(const float* __restrict__ padded,
                 const int*   __restrict__ seq_lengths,
                 const float* __restrict__ enc_Wih,
                 const float* __restrict__ enc_Whh,
                 const float* __restrict__ enc_b,
                 const float* __restrict__ enc_linW,
                 const float* __restrict__ enc_linb,
                 const float* __restrict__ dec_linW,
                 const float* __restrict__ dec_linb,
                 const float* __restrict__ dec_Wih,
                 const float* __restrict__ dec_Whh,
                 const float* __restrict__ dec_b,
                 const float* __restrict__ outW,
                 const float* __restrict__ outb,
                 float* __restrict__ out) {
    __shared__ float4    hb4[NB][2][Hn / 4];  // per-batch ping-pong h
    __shared__ float4    sh_ow4[Hn / 4];      // outW
    __shared__ float     xbuf[NB][Tn];        // input sequences
    __shared__ float     sh_hz[NB][4];        // bottleneck hz
    __shared__ unsigned  s_last;
    __shared__ double    red_s[256];
    __shared__ long long red_c[256];

    const int t    = threadIdx.x;
    const int u    = t >> 2;               // hidden unit (0..63)
    const int qi   = t & 3;                // gate index
    const int row  = qi * Hn + u;          // gate row
    const int lane = t & 31;
    const int wid  = t >> 5;

    float* sh_ow = (float*)sh_ow4;

    int  bs_[NB];
    bool val[NB];
    int  sl[NB];
#pragma unroll
    for (int j = 0; j < NB; j++) {
        int idx = NB * blockIdx.x + j;
        val[j] = (idx < Bn);
        bs_[j] = g_perm[val[j] ? idx : 0];
        sl[j]  = val[j] ? seq_lengths[bs_[j]] : 0;
    }
    const int smax = max(sl[0], max(sl[1], sl[2]));

    // Prefetch sequences (+ emit padded copies), init state, stage outW.
    for (int i = t; i < Tn; i += 256) {
#pragma unroll
        for (int j = 0; j < NB; j++) {
            float v = padded[(size_t)bs_[j] * Tn + i];
            xbuf[j][i] = v;
            if (val[j]) out[1 + (size_t)bs_[j] * Tn + i] = v;
        }
    }
    if (t < Hn) {
#pragma unroll
        for (int j = 0; j < NB; j++) ((float*)hb4[j][0])[t] = 0.0f;
        sh_ow[t] = outW[t];
    }

    // Encoder weights: one row (64 floats = 32 ull) in registers.
    unsigned long long w[32];
    {
        const float4* wp = (const float4*)(enc_Whh + row * Hn);
#pragma unroll
        for (int k = 0; k < 16; k++) {
            float4 v = wp[k];
            w[2 * k]     = pack2(v.x, v.y);
            w[2 * k + 1] = pack2(v.z, v.w);
        }
    }
    float wih  = enc_Wih[row];
    float bias = enc_b[row];
    float c_[NB]  = {0.0f, 0.0f, 0.0f};    // cell state (qi==0 lanes)
    float hc_[NB] = {0.0f, 0.0f, 0.0f};    // frozen-forward h of unit u

    __syncthreads();

    // ---- encoder: run to max seqlen; per-batch freeze ----
    for (int s = 0; s < smax; s++) {
        unsigned long long a0[NB], a1[NB];
#pragma unroll
        for (int j = 0; j < NB; j++) { a0[j] = 0ull; a1[j] = 0ull; }

        const ulonglong2* hq0 = (const ulonglong2*)hb4[0][s & 1];
        const ulonglong2* hq1 = (const ulonglong2*)hb4[1][s & 1];
        const ulonglong2* hq2 = (const ulonglong2*)hb4[2][s & 1];
#pragma unroll
        for (int k = 0; k < 16; k++) {
            ulonglong2 h0 = hq0[k];        // uniform-address broadcast LDS.128
            ulonglong2 h1 = hq1[k];
            ulonglong2 h2 = hq2[k];
            ffma2(a0[0], w[2 * k], h0.x);  ffma2(a1[0], w[2 * k + 1], h0.y);
            ffma2(a0[1], w[2 * k], h1.x);  ffma2(a1[1], w[2 * k + 1], h1.y);
            ffma2(a0[2], w[2 * k], h2.x);  ffma2(a1[2], w[2 * k + 1], h2.y);
        }

#pragma unroll
        for (int j = 0; j < NB; j++) {
            float s0, s1;
            unpack2(add2(a0[j], a1[j]), s0, s1);
            float gv = (s0 + s1) + __fmaf_rn(xbuf[j][s], wih, bias);

            float arg = (qi == 2) ? gv : 0.5f * gv;       // g->tanh, else sigm
            float tv  = tanh_hw(arg);
            float av  = (qi == 2) ? tv : __fmaf_rn(tv, 0.5f, 0.5f);

            float fs = __shfl_xor_sync(0xffffffffu, av, 1);  // qi0 <- sig(f)
            float gt = __shfl_xor_sync(0xffffffffu, av, 2);  // qi0 <- tanh(g)
            float os = __shfl_xor_sync(0xffffffffu, av, 3);  // qi0 <- sig(o)
            if (qi == 0) {
                if (s < sl[j]) {
                    c_[j]  = __fmaf_rn(fs, c_[j], av * gt);
                    hc_[j] = os * tanh_hw(c_[j]);
                }
                ((float*)hb4[j][(s + 1) & 1])[u] = hc_[j];
            }
        }
        __syncthreads();
    }

    // ---- bottleneck: warp j computes hz for batch j (lanes 0..2) ----
    if (wid < NB && lane < 3) {
        const float* hf = (const float*)hb4[wid][smax & 1];
        float s = enc_linb[lane];
        const float* wl = enc_linW + lane * Hn;
#pragma unroll 16
        for (int j = 0; j < Hn; j++) s = __fmaf_rn(wl[j], hf[j], s);
        float z = sigm(s);
        sh_hz[wid][lane] = z;
        if (val[wid])
            out[1 + 2 * (size_t)Bn * Tn + (size_t)bs_[wid] * 3 + lane] = z;
    }
    __syncthreads();

    // hd -> slot 0 per batch (c carries over). threads 0..191: j = t>>6.
    if (t < NB * Hn) {
        int j = t >> 6, i = t & 63;
        ((float*)hb4[j][0])[i] = dec_linb[i]
            + dec_linW[i * 3 + 0] * sh_hz[j][0]
            + dec_linW[i * 3 + 1] * sh_hz[j][1]
            + dec_linW[i * 3 + 2] * sh_hz[j][2];
    }

    // Decoder weights, FOLDED: W' = dec_Whh + dec_Wih (x) outW,
    // b' = dec_b + dec_Wih*outb (shared by all batches).
    float wih2 = dec_Wih[row];
    {
        const float4* wp = (const float4*)(dec_Whh + row * Hn);
#pragma unroll
        for (int k = 0; k < 16; k++) {
            float4 v = wp[k], o = sh_ow4[k];
            w[2 * k]     = pack2(__fmaf_rn(wih2, o.x, v.x), __fmaf_rn(wih2, o.y, v.y));
            w[2 * k + 1] = pack2(__fmaf_rn(wih2, o.z, v.z), __fmaf_rn(wih2, o.w, v.w));
        }
    }
    float ob = outb[0];
    bias = __fmaf_rn(wih2, ob, dec_b[row]);

    float ow0 = sh_ow[lane];
    float ow1 = sh_ow[lane + 32];
    __syncthreads();

    // qs_j = outW . hd_j + outb (step-0 correction: true x_0 = 0).
    float qs[NB] = {ob, ob, ob};
    {
        const float* hd0 = (const float*)hb4[0][0];
        const float* hd1 = (const float*)hb4[1][0];
        const float* hd2 = (const float*)hb4[2][0];
#pragma unroll 16
        for (int j = 0; j < Hn; j++) {
            float o = sh_ow[j];
            qs[0] = __fmaf_rn(o, hd0[j], qs[0]);
            qs[1] = __fmaf_rn(o, hd1[j], qs[1]);
            qs[2] = __fmaf_rn(o, hd2[j], qs[2]);
        }
    }

    // ---- decoder: T steps; warps 0/1/2 emit y for b0/b1/b2 one step late ----
    float lacc = 0.0f;                     // lane0 of warps 0..2

    for (int s = 0; s < Tn; s++) {
        // lagged y projection, off the recurrence critical path
        if (s > 0 && wid < NB) {
            const float* hr = (const float*)hb4[wid][s & 1];
            float yp = hr[lane] * ow0 + hr[lane + 32] * ow1;
            yp += __shfl_xor_sync(0xffffffffu, yp, 16);
            yp += __shfl_xor_sync(0xffffffffu, yp, 8);
            yp += __shfl_xor_sync(0xffffffffu, yp, 4);
            yp += __shfl_xor_sync(0xffffffffu, yp, 2);
            yp += __shfl_xor_sync(0xffffffffu, yp, 1);
            if (lane == 0 && val[wid]) {
                float y = yp + ob;
                out[1 + (size_t)Bn * Tn + (size_t)bs_[wid] * Tn + (s - 1)] = y;
                if (s - 1 < sl[wid]) {
                    float d = xbuf[wid][s - 1] - y;
                    lacc = __fmaf_rn(d, d, lacc);
                }
            }
        }

        unsigned long long a0[NB], a1[NB];
#pragma unroll
        for (int j = 0; j < NB; j++) { a0[j] = 0ull; a1[j] = 0ull; }

        const ulonglong2* hq0 = (const ulonglong2*)hb4[0][s & 1];
        const ulonglong2* hq1 = (const ulonglong2*)hb4[1][s & 1];
        const ulonglong2* hq2 = (const ulonglong2*)hb4[2][s & 1];
#pragma unroll
        for (int k = 0; k < 16; k++) {
            ulonglong2 h0 = hq0[k];
            ulonglong2 h1 = hq1[k];
            ulonglong2 h2 = hq2[k];
            ffma2(a0[0], w[2 * k], h0.x);  ffma2(a1[0], w[2 * k + 1], h0.y);
            ffma2(a0[1], w[2 * k], h1.x);  ffma2(a1[1], w[2 * k + 1], h1.y);
            ffma2(a0[2], w[2 * k], h2.x);  ffma2(a1[2], w[2 * k + 1], h2.y);
        }

#pragma unroll
        for (int j = 0; j < NB; j++) {
            float s0, s1;
            unpack2(add2(a0[j], a1[j]), s0, s1);
            float gv = (s0 + s1) + bias;
            if (s == 0) gv = __fmaf_rn(-wih2, qs[j], gv);  // undo fold: x_0=0

            float arg = (qi == 2) ? gv : 0.5f * gv;
            float tv  = tanh_hw(arg);
            float av  = (qi == 2) ? tv : __fmaf_rn(tv, 0.5f, 0.5f);

            float fs = __shfl_xor_sync(0xffffffffu, av, 1);
            float gt = __shfl_xor_sync(0xffffffffu, av, 2);
            float os = __shfl_xor_sync(0xffffffffu, av, 3);
            if (qi == 0) {
                c_[j] = __fmaf_rn(fs, c_[j], av * gt);
                ((float*)hb4[j][(s + 1) & 1])[u] = os * tanh_hw(c_[j]);
            }
        }
        __syncthreads();
    }

    // Tail: y_{T-1} from slot Tn&1 = 0.
    if (wid < NB) {
        const float* hr = (const float*)hb4[wid][Tn & 1];
        float yp = hr[lane] * ow0 + hr[lane + 32] * ow1;
        yp += __shfl_xor_sync(0xffffffffu, yp, 16);
        yp += __shfl_xor_sync(0xffffffffu, yp, 8);
        yp += __shfl_xor_sync(0xffffffffu, yp, 4);
        yp += __shfl_xor_sync(0xffffffffu, yp, 2);
        yp += __shfl_xor_sync(0xffffffffu, yp, 1);
        if (lane == 0 && val[wid]) {
            float y = yp + ob;
            out[1 + (size_t)Bn * Tn + (size_t)bs_[wid] * Tn + (Tn - 1)] = y;
            if (Tn - 1 < sl[wid]) {
                float d = xbuf[wid][Tn - 1] - y;
                lacc = __fmaf_rn(d, d, lacc);
            }
            g_partial[bs_[wid]] = lacc;
        }
    }

    // ---- last-CTA deterministic loss finalize ----
    __threadfence();
    if (t == 0) s_last = atomicInc(&g_done, NCTA - 1);   // wraps to 0 each run
    __syncthreads();
    if (s_last == NCTA - 1) {
        __threadfence();
        double    s = 0.0;
        long long c = 0;
        for (int i = t; i < Bn; i += 256) {              // fixed order
            s += (double)g_partial[i];
            c += (long long)seq_lengths[i];
        }
        red_s[t] = s;
        red_c[t] = c;
        __syncthreads();
        for (int off = 128; off; off >>= 1) {            // fixed tree
            if (t < off) {
                red_s[t] += red_s[t + off];
                red_c[t] += red_c[t + off];
            }
            __syncthreads();
        }
        if (t == 0) out[0] = (float)(red_s[0] / (double)red_c[0]);
    }
}

extern "C" void kernel_launch(void* const* d_in, const int* in_sizes, int n_in,
                              void* d_out, int out_size) {
    const float* padded   = (const float*)d_in[0];
    const int*   seql     = (const int*)  d_in[1];
    const float* enc_Wih  = (const float*)d_in[2];
    const float* enc_Whh  = (const float*)d_in[3];
    const float* enc_b    = (const float*)d_in[4];
    const float* enc_linW = (const float*)d_in[5];
    const float* enc_linb = (const float*)d_in[6];
    const float* dec_linW = (const float*)d_in[7];
    const float* dec_linb = (const float*)d_in[8];
    const float* dec_Wih  = (const float*)d_in[9];
    const float* dec_Whh  = (const float*)d_in[10];
    const float* dec_b    = (const float*)d_in[11];
    const float* outW     = (const float*)d_in[12];
    const float* outb     = (const float*)d_in[13];
    float* out = (float*)d_out;

    sort_kernel<<<1, 1024>>>(seql);
    lstm_kernel<<<NCTA, 256>>>(padded, seql,
                               enc_Wih, enc_Whh, enc_b,
                               enc_linW, enc_linb,
                               dec_linW, dec_linb,
                               dec_Wih, dec_Whh, dec_b,
                               outW, outb, out);
}